// round 12
// baseline (speedup 1.0000x reference)
#include <cuda_runtime.h>
#include <cuda_fp16.h>
#include <stdint.h>
#include <math.h>

#define C_CH  256
#define OUT_H 7
#define OUT_W 35
#define ENTRIES (OUT_W * 4 * 4)   // 560 descriptors per (roi, ph)

// -------- channel-last fp16 scratch (static; +256 halfs zero pad) --------
__device__ __half g_h0[(size_t)2 * 256 * 256 * 256 + 256];
__device__ __half g_h1[(size_t)2 * 256 * 128 * 128 + 256];
__device__ __half g_h2[(size_t)2 * 256 *  64 *  64 + 256];
__device__ __half g_h3[(size_t)2 * 256 *  32 *  32 + 256];

#define NB0 16384
#define NB1 4096
#define NB2 1024
#define NB3 256
#define NB_ALL (NB0 + NB1 + NB2 + NB3)

// Fused NCHW fp32 -> NHWC fp16 transpose for all 4 levels + pad-zero block.
__global__ __launch_bounds__(256)
void transpose_all_kernel(const float* __restrict__ f0,
                          const float* __restrict__ f1,
                          const float* __restrict__ f2,
                          const float* __restrict__ f3)
{
    const int bid = blockIdx.x;
    if (bid == NB_ALL) {                 // zero the overrun pads
        const int t = threadIdx.y * 32 + threadIdx.x;
        g_h0[(size_t)2 * 256 * 256 * 256 + t] = __float2half(0.f);
        g_h1[(size_t)2 * 256 * 128 * 128 + t] = __float2half(0.f);
        g_h2[(size_t)2 * 256 *  64 *  64 + t] = __float2half(0.f);
        g_h3[(size_t)2 * 256 *  32 *  32 + t] = __float2half(0.f);
        return;
    }

    __shared__ float tile[64][33];
    int lev, rel;
    if      (bid < NB0)             { lev = 0; rel = bid; }
    else if (bid < NB0 + NB1)       { lev = 1; rel = bid - NB0; }
    else if (bid < NB0 + NB1 + NB2) { lev = 2; rel = bid - NB0 - NB1; }
    else                            { lev = 3; rel = bid - NB0 - NB1 - NB2; }

    const int Hc  = 256 >> lev;
    const int HW  = Hc * Hc;
    const int pxb = HW / 32;
    const int p0  = (rel % pxb) * 32;
    const int t   = rel / pxb;          // 0..7
    const int c0  = (t & 3) * 64;
    const int b   = t >> 2;

    const float* __restrict__ in = (lev == 0) ? f0 : (lev == 1) ? f1
                                 : (lev == 2) ? f2 : f3;
    __half* __restrict__ outp = (lev == 0) ? g_h0 : (lev == 1) ? g_h1
                              : (lev == 2) ? g_h2 : g_h3;

    const int tx = threadIdx.x;
    const int ty = threadIdx.y;

    const float* __restrict__ ip = in + ((size_t)b * C_CH + c0) * HW + p0;
    #pragma unroll
    for (int k = 0; k < 8; ++k) {
        const int c = ty + 8 * k;
        tile[c][tx] = __ldg(ip + (size_t)c * HW + tx);
    }
    __syncthreads();

    const int tid = ty * 32 + tx;
    const int cl  = tid & 31;
    const int r   = tid >> 5;
    __half2* __restrict__ op =
        (__half2*)(outp + ((size_t)b * HW + p0) * C_CH + c0) + cl;
    #pragma unroll
    for (int m = 0; m < 4; ++m) {
        const int pix = r + 8 * m;
        op[(size_t)pix * (C_CH / 2)] =
            __floats2half2_rn(tile[2 * cl][pix], tile[2 * cl + 1][pix]);
    }
}

__device__ __forceinline__ __half2 u32_as_h2(unsigned int u)
{
    return *(__half2*)&u;
}
__device__ __forceinline__ unsigned int h2_as_u32(__half2 h)
{
    return *(unsigned int*)&h;
}

// -------- main kernel: block = (roi n, channel-half, ph-split) --------
// 160 threads = 5 warps x 7 pw. Lane pairs: lanes 0-15 fetch tap x0's
// 128-ch half, lanes 16-31 fetch tap x1's (adjacent pixel) -> one LDG.128
// serves two bilinear taps. Half-warp partials merged via shfl.xor(16).
__global__ __launch_bounds__(160, 5)
void rroi_main_kernel(const float* __restrict__ rois, float* __restrict__ out)
{
    __shared__ uint4 s_desc[ENTRIES];   // {pair0, pair1, w00|w01, w10|w11}
    __shared__ float s_out[OUT_W * 129];

    const int n    = blockIdx.x;
    const int half = blockIdx.y;        // channels half*128 .. +127
    const int h16  = half * 16;         // uint4 offset within a pixel row
    const int tid  = threadIdx.x;
    const int lane = tid & 31;
    const int wrp  = tid >> 5;          // 0..4

    const int lane_off = lane + (lane & 16);             // pair addressing
    const unsigned int psel = (lane < 16) ? 0x1010u : 0x3232u;  // PRMT dup sel

    const float r1 = __ldg(rois + n * 6 + 1);
    const float r2 = __ldg(rois + n * 6 + 2);
    const float r3 = __ldg(rois + n * 6 + 3);
    const float r4 = __ldg(rois + n * 6 + 4);
    const float r5 = __ldg(rois + n * 6 + 5);
    const int   b  = (int)__ldg(rois + n * 6 + 0);
    float sint, cost;
    sincosf(r5, &sint, &cost);

    const uint4* __restrict__ T0 = (const uint4*)g_h0;
    const uint4* __restrict__ T1 = (const uint4*)g_h1;
    const uint4* __restrict__ T2 = (const uint4*)g_h2;
    const uint4* __restrict__ T3 = (const uint4*)g_h3;

    const int ph_lo = blockIdx.z ? 4 : 0;
    const int ph_hi = blockIdx.z ? OUT_H : 4;

    for (int ph = ph_lo; ph < ph_hi; ++ph) {
        // ---- Phase 1: descriptors for this ph ----
        for (int e = tid; e < ENTRIES; e += 160) {
            const int pw  = e % OUT_W;
            const int q   = e / OUT_W;
            const int lev = q >> 2;
            const int s   = q & 3;
            const int sy  = s >> 1;
            const int sx  = s & 1;

            const int   Hc = 256 >> lev;
            const int   HW = Hc * Hc;
            const float sc = 0.25f / (float)(1 << lev);

            const float cx = r1 * sc;
            const float cy = r2 * sc;
            const float w  = fmaxf(r3 * sc, 1.0f);
            const float h  = fmaxf(r4 * sc, 1.0f);

            const float gy = (float)ph + ((float)sy + 0.5f) * 0.5f;
            const float gx = (float)pw + ((float)sx + 0.5f) * 0.5f;
            const float yy = gy * (h * (1.0f / OUT_H)) - 0.5f * h;
            const float xx = gx * (w * (1.0f / OUT_W)) - 0.5f * w;

            float x = xx * cost - yy * sint + cx;
            float y = xx * sint + yy * cost + cy;

            const float Hf = (float)Hc;
            const bool valid = (y >= -1.0f) && (y <= Hf) && (x >= -1.0f) && (x <= Hf);
            y = fminf(fmaxf(y, 0.0f), Hf - 1.0f);
            x = fminf(fmaxf(x, 0.0f), Hf - 1.0f);

            const int y0 = (int)floorf(y);
            const int x0 = (int)floorf(x);
            const int y1 = min(y0 + 1, Hc - 1);
            const float ly = y - (float)y0;
            const float lx = x - (float)x0;
            const float hy = 1.0f - ly;
            const float hx = 1.0f - lx;
            const float qv = valid ? 0.25f : 0.0f;

            float w00 = hy * hx * qv, w01 = hy * lx * qv;
            float w10 = ly * hx * qv, w11 = ly * lx * qv;
            if (x0 == Hc - 1) {          // x-clamp: fold x1 tap into x0
                w00 += w01; w01 = 0.f;
                w10 += w11; w11 = 0.f;
            }

            const int base = b * HW;
            s_desc[e] = make_uint4(
                (unsigned)((base + y0 * Hc + x0) * 32 + h16),
                (unsigned)((base + y1 * Hc + x0) * 32 + h16),
                h2_as_u32(__halves2half2(__float2half_rn(w00), __float2half_rn(w01))),
                h2_as_u32(__halves2half2(__float2half_rn(w10), __float2half_rn(w11))));
        }
        __syncthreads();

        // ---- Phase 2: paired gathers ----
        #pragma unroll
        for (int pwi = 0; pwi < 7; ++pwi) {
            const int pw = wrp * 7 + pwi;
            float best[8];
            #pragma unroll
            for (int lev = 0; lev < 4; ++lev) {
                const uint4* __restrict__ T =
                    (lev == 0) ? T0 : (lev == 1) ? T1 : (lev == 2) ? T2 : T3;
                float acc[8] = {0.f, 0.f, 0.f, 0.f, 0.f, 0.f, 0.f, 0.f};
                #pragma unroll
                for (int s2 = 0; s2 < 2; ++s2) {
                    __half2 a[4];
                    a[0] = __float2half2_rn(0.f);
                    a[1] = a[0]; a[2] = a[0]; a[3] = a[0];
                    #pragma unroll
                    for (int ss = 0; ss < 2; ++ss) {
                        const int e = (lev * 4 + s2 * 2 + ss) * OUT_W + pw;
                        const uint4 d = s_desc[e];
                        const __half2 wA = u32_as_h2(__byte_perm(d.z, 0, psel));
                        const __half2 wB = u32_as_h2(__byte_perm(d.w, 0, psel));
                        const uint4 rA = __ldg(T + d.x + lane_off);
                        const uint4 rB = __ldg(T + d.y + lane_off);
                        a[0] = __hfma2(wA, u32_as_h2(rA.x), a[0]);
                        a[1] = __hfma2(wA, u32_as_h2(rA.y), a[1]);
                        a[2] = __hfma2(wA, u32_as_h2(rA.z), a[2]);
                        a[3] = __hfma2(wA, u32_as_h2(rA.w), a[3]);
                        a[0] = __hfma2(wB, u32_as_h2(rB.x), a[0]);
                        a[1] = __hfma2(wB, u32_as_h2(rB.y), a[1]);
                        a[2] = __hfma2(wB, u32_as_h2(rB.z), a[2]);
                        a[3] = __hfma2(wB, u32_as_h2(rB.w), a[3]);
                    }
                    #pragma unroll
                    for (int k = 0; k < 4; ++k) {
                        const float2 f = __half22float2(a[k]);
                        acc[2 * k]     += f.x;
                        acc[2 * k + 1] += f.y;
                    }
                }
                // merge half-warp tap partials (x0 side + x1 side)
                #pragma unroll
                for (int j = 0; j < 8; ++j)
                    acc[j] += __shfl_xor_sync(0xffffffffu, acc[j], 16);
                #pragma unroll
                for (int j = 0; j < 8; ++j)
                    best[j] = (lev == 0) ? acc[j] : fmaxf(best[j], acc[j]);
            }
            if (lane < 16) {
                #pragma unroll
                for (int j = 0; j < 8; ++j)
                    s_out[pw * 129 + lane * 8 + j] = best[j];
            }
        }
        __syncthreads();

        // ---- Phase 3: coalesced output write for this ph ----
        float* __restrict__ ob =
            out + (((size_t)n * C_CH + half * 128) * OUT_H + ph) * OUT_W;
        for (int idx = tid; idx < 128 * OUT_W; idx += 160) {
            const int c  = idx / OUT_W;
            const int pw = idx - c * OUT_W;
            ob[(size_t)c * (OUT_H * OUT_W) + pw] = s_out[pw * 129 + c];
        }
        __syncthreads();
    }
}

extern "C" void kernel_launch(void* const* d_in, const int* in_sizes, int n_in,
                              void* d_out, int out_size)
{
    const float* f0   = (const float*)d_in[0];
    const float* f1   = (const float*)d_in[1];
    const float* f2   = (const float*)d_in[2];
    const float* f3   = (const float*)d_in[3];
    const float* rois = (const float*)d_in[4];
    float* out = (float*)d_out;

    const int N = in_sizes[4] / 6;

    transpose_all_kernel<<<NB_ALL + 1, dim3(32, 8)>>>(f0, f1, f2, f3);
    rroi_main_kernel<<<dim3(N, 2, 2), 160>>>(rois, out);
}

// round 13
// speedup vs baseline: 1.1107x; 1.1107x over previous
#include <cuda_runtime.h>
#include <cuda_fp16.h>
#include <stdint.h>
#include <math.h>

#define C_CH  256
#define OUT_H 7
#define OUT_W 35
#define ENTRIES (OUT_W * 4 * 4)   // 560 descriptors per (roi, ph)

// -------- channel-last fp16 scratch (static: allocation-free) --------
__device__ __half g_h0[(size_t)2 * 256 * 256 * 256];  // 67MB
__device__ __half g_h1[(size_t)2 * 256 * 128 * 128];  // 16.8MB
__device__ __half g_h2[(size_t)2 * 256 *  64 *  64];  // 4.2MB
__device__ __half g_h3[(size_t)2 * 256 *  32 *  32];  // 1.05MB

#define NB0 16384
#define NB1 4096
#define NB2 1024
#define NB3 256
#define NB_ALL (NB0 + NB1 + NB2 + NB3)

// Fused NCHW fp32 -> NHWC fp16 transpose for all 4 levels, 1D grid.
__global__ __launch_bounds__(256)
void transpose_all_kernel(const float* __restrict__ f0,
                          const float* __restrict__ f1,
                          const float* __restrict__ f2,
                          const float* __restrict__ f3)
{
    __shared__ float tile[64][33];
    const int bid = blockIdx.x;
    int lev, rel;
    if      (bid < NB0)             { lev = 0; rel = bid; }
    else if (bid < NB0 + NB1)       { lev = 1; rel = bid - NB0; }
    else if (bid < NB0 + NB1 + NB2) { lev = 2; rel = bid - NB0 - NB1; }
    else                            { lev = 3; rel = bid - NB0 - NB1 - NB2; }

    const int Hc  = 256 >> lev;
    const int HW  = Hc * Hc;
    const int pxb = HW / 32;
    const int p0  = (rel % pxb) * 32;
    const int t   = rel / pxb;          // 0..7
    const int c0  = (t & 3) * 64;
    const int b   = t >> 2;

    const float* __restrict__ in = (lev == 0) ? f0 : (lev == 1) ? f1
                                 : (lev == 2) ? f2 : f3;
    __half* __restrict__ outp = (lev == 0) ? g_h0 : (lev == 1) ? g_h1
                              : (lev == 2) ? g_h2 : g_h3;

    const int tx = threadIdx.x;
    const int ty = threadIdx.y;

    const float* __restrict__ ip = in + ((size_t)b * C_CH + c0) * HW + p0;
    #pragma unroll
    for (int k = 0; k < 8; ++k) {
        const int c = ty + 8 * k;
        tile[c][tx] = __ldg(ip + (size_t)c * HW + tx);
    }
    __syncthreads();

    const int tid = ty * 32 + tx;
    const int cl  = tid & 31;            // channel pair
    const int r   = tid >> 5;            // 0..7
    __half2* __restrict__ op =
        (__half2*)(outp + ((size_t)b * HW + p0) * C_CH + c0) + cl;
    #pragma unroll
    for (int m = 0; m < 4; ++m) {
        const int pix = r + 8 * m;
        op[(size_t)pix * (C_CH / 2)] =
            __floats2half2_rn(tile[2 * cl][pix], tile[2 * cl + 1][pix]);
    }
}

__device__ __forceinline__ unsigned int h2_as_u32(__half2 h)
{
    return *(unsigned int*)&h;
}

// One fp16 tap over 128 channels: lane owns 4 ch (uint2 = 8B).
__device__ __forceinline__ void tap2(const uint2* __restrict__ T,
                                     int p, __half2 w, __half2 a[2])
{
    const uint2 r = __ldg(T + p);
    a[0] = __hfma2(w, *(const __half2*)&r.x, a[0]);
    a[1] = __hfma2(w, *(const __half2*)&r.y, a[1]);
}

// -------- main kernel: block = (roi n, channel-half), 224 threads --------
// Loops ph = 0..6 internally -> cross-row L1 reuse of pixel lines.
// warp w handles pw = w*5 .. w*5+4; lane owns 4 channels.
// 8 taps (2 samples) accumulate in half2 before one fp32 conversion.
__global__ __launch_bounds__(224, 4)
void rroi_main_kernel(const float* __restrict__ rois, float* __restrict__ out)
{
    __shared__ int4  s_pix[ENTRIES];    // 4 tap indices, pre-scaled uint2 units
    __shared__ uint4 s_wt[ENTRIES];     // 4 weights as duplicated half2
    __shared__ float s_out[OUT_W * 129];

    const int n    = blockIdx.x;
    const int half = blockIdx.y;        // 0 or 1 -> channels half*128..+127
    const int h32  = half * 32;         // uint2 offset of this half within a pixel
    const int tid  = threadIdx.x;
    const int lane = tid & 31;
    const int wrp  = tid >> 5;

    const float r1 = __ldg(rois + n * 6 + 1);
    const float r2 = __ldg(rois + n * 6 + 2);
    const float r3 = __ldg(rois + n * 6 + 3);
    const float r4 = __ldg(rois + n * 6 + 4);
    const float r5 = __ldg(rois + n * 6 + 5);
    const int   b  = (int)__ldg(rois + n * 6 + 0);
    float sint, cost;
    sincosf(r5, &sint, &cost);

    const uint2* __restrict__ T0 = (const uint2*)g_h0;
    const uint2* __restrict__ T1 = (const uint2*)g_h1;
    const uint2* __restrict__ T2 = (const uint2*)g_h2;
    const uint2* __restrict__ T3 = (const uint2*)g_h3;

    for (int ph = 0; ph < OUT_H; ++ph) {
        // ---- Phase 1: descriptors for this ph ----
        for (int e = tid; e < ENTRIES; e += 224) {
            const int pw  = e % OUT_W;
            const int q   = e / OUT_W;
            const int lev = q >> 2;
            const int s   = q & 3;
            const int sy  = s >> 1;
            const int sx  = s & 1;

            const int   Hc = 256 >> lev;
            const int   HW = Hc * Hc;
            const float sc = 0.25f / (float)(1 << lev);

            const float cx = r1 * sc;
            const float cy = r2 * sc;
            const float w  = fmaxf(r3 * sc, 1.0f);
            const float h  = fmaxf(r4 * sc, 1.0f);

            const float gy = (float)ph + ((float)sy + 0.5f) * 0.5f;
            const float gx = (float)pw + ((float)sx + 0.5f) * 0.5f;
            const float yy = gy * (h * (1.0f / OUT_H)) - 0.5f * h;
            const float xx = gx * (w * (1.0f / OUT_W)) - 0.5f * w;

            float x = xx * cost - yy * sint + cx;
            float y = xx * sint + yy * cost + cy;

            const float Hf = (float)Hc;
            const bool valid = (y >= -1.0f) && (y <= Hf) && (x >= -1.0f) && (x <= Hf);
            y = fminf(fmaxf(y, 0.0f), Hf - 1.0f);
            x = fminf(fmaxf(x, 0.0f), Hf - 1.0f);

            const int y0 = (int)floorf(y);
            const int x0 = (int)floorf(x);
            const int y1 = min(y0 + 1, Hc - 1);
            const int x1 = min(x0 + 1, Hc - 1);
            const float ly = y - (float)y0;
            const float lx = x - (float)x0;
            const float hy = 1.0f - ly;
            const float hx = 1.0f - lx;
            const float qv = valid ? 0.25f : 0.0f;

            const int base = b * HW;
            s_pix[e] = make_int4((base + y0 * Hc + x0) * 64 + h32,
                                 (base + y0 * Hc + x1) * 64 + h32,
                                 (base + y1 * Hc + x0) * 64 + h32,
                                 (base + y1 * Hc + x1) * 64 + h32);
            s_wt[e] = make_uint4(h2_as_u32(__float2half2_rn(hy * hx * qv)),
                                 h2_as_u32(__float2half2_rn(hy * lx * qv)),
                                 h2_as_u32(__float2half2_rn(ly * hx * qv)),
                                 h2_as_u32(__float2half2_rn(ly * lx * qv)));
        }
        __syncthreads();

        // ---- Phase 2: gathers ----
        #pragma unroll
        for (int pwi = 0; pwi < 5; ++pwi) {
            const int pw = wrp * 5 + pwi;
            float best[4];
            #pragma unroll
            for (int lev = 0; lev < 4; ++lev) {
                const uint2* __restrict__ T =
                    (lev == 0) ? T0 : (lev == 1) ? T1 : (lev == 2) ? T2 : T3;
                float acc[4] = {0.f, 0.f, 0.f, 0.f};
                #pragma unroll
                for (int s2 = 0; s2 < 2; ++s2) {   // 2 samples per half2 chain
                    __half2 a[2];
                    a[0] = __float2half2_rn(0.f); a[1] = a[0];
                    #pragma unroll
                    for (int ss = 0; ss < 2; ++ss) {
                        const int e = (lev * 4 + s2 * 2 + ss) * OUT_W + pw;
                        const int4  p = s_pix[e];
                        const uint4 w = s_wt[e];
                        tap2(T, p.x + lane, *(const __half2*)&w.x, a);
                        tap2(T, p.y + lane, *(const __half2*)&w.y, a);
                        tap2(T, p.z + lane, *(const __half2*)&w.z, a);
                        tap2(T, p.w + lane, *(const __half2*)&w.w, a);
                    }
                    #pragma unroll
                    for (int k = 0; k < 2; ++k) {
                        const float2 f = __half22float2(a[k]);
                        acc[2 * k]     += f.x;
                        acc[2 * k + 1] += f.y;
                    }
                }
                #pragma unroll
                for (int j = 0; j < 4; ++j)
                    best[j] = (lev == 0) ? acc[j] : fmaxf(best[j], acc[j]);
            }
            #pragma unroll
            for (int j = 0; j < 4; ++j)
                s_out[pw * 129 + lane * 4 + j] = best[j];
        }
        __syncthreads();

        // ---- Phase 3: coalesced output write for this ph ----
        float* __restrict__ ob =
            out + (((size_t)n * C_CH + half * 128) * OUT_H + ph) * OUT_W;
        for (int idx = tid; idx < 128 * OUT_W; idx += 224) {
            const int c  = idx / OUT_W;
            const int pw = idx - c * OUT_W;
            ob[(size_t)c * (OUT_H * OUT_W) + pw] = s_out[pw * 129 + c];
        }
        __syncthreads();
    }
}

extern "C" void kernel_launch(void* const* d_in, const int* in_sizes, int n_in,
                              void* d_out, int out_size)
{
    const float* f0   = (const float*)d_in[0];
    const float* f1   = (const float*)d_in[1];
    const float* f2   = (const float*)d_in[2];
    const float* f3   = (const float*)d_in[3];
    const float* rois = (const float*)d_in[4];
    float* out = (float*)d_out;

    const int N = in_sizes[4] / 6;

    transpose_all_kernel<<<NB_ALL, dim3(32, 8)>>>(f0, f1, f2, f3);
    rroi_main_kernel<<<dim3(N, 2), 224>>>(rois, out);
}

// round 14
// speedup vs baseline: 1.1238x; 1.0118x over previous
#include <cuda_runtime.h>
#include <cuda_fp16.h>
#include <stdint.h>
#include <math.h>

#define C_CH  256
#define OUT_H 7
#define OUT_W 35
#define ENTRIES (OUT_W * 4 * 4)   // 560 descriptors per (roi, ph)

// -------- channel-last fp16 scratch (static: allocation-free) --------
__device__ __half g_h0[(size_t)2 * 256 * 256 * 256];  // 67MB
__device__ __half g_h1[(size_t)2 * 256 * 128 * 128];  // 16.8MB
__device__ __half g_h2[(size_t)2 * 256 *  64 *  64];  // 4.2MB
__device__ __half g_h3[(size_t)2 * 256 *  32 *  32];  // 1.05MB

#define NB0 16384
#define NB1 4096
#define NB2 1024
#define NB3 256
#define NB_ALL (NB0 + NB1 + NB2 + NB3)

// Fused NCHW fp32 -> NHWC fp16 transpose for all 4 levels, 1D grid.
__global__ __launch_bounds__(256)
void transpose_all_kernel(const float* __restrict__ f0,
                          const float* __restrict__ f1,
                          const float* __restrict__ f2,
                          const float* __restrict__ f3)
{
    __shared__ float tile[64][33];
    const int bid = blockIdx.x;
    int lev, rel;
    if      (bid < NB0)             { lev = 0; rel = bid; }
    else if (bid < NB0 + NB1)       { lev = 1; rel = bid - NB0; }
    else if (bid < NB0 + NB1 + NB2) { lev = 2; rel = bid - NB0 - NB1; }
    else                            { lev = 3; rel = bid - NB0 - NB1 - NB2; }

    const int Hc  = 256 >> lev;
    const int HW  = Hc * Hc;
    const int pxb = HW / 32;
    const int p0  = (rel % pxb) * 32;
    const int t   = rel / pxb;          // 0..7
    const int c0  = (t & 3) * 64;
    const int b   = t >> 2;

    const float* __restrict__ in = (lev == 0) ? f0 : (lev == 1) ? f1
                                 : (lev == 2) ? f2 : f3;
    __half* __restrict__ outp = (lev == 0) ? g_h0 : (lev == 1) ? g_h1
                              : (lev == 2) ? g_h2 : g_h3;

    const int tx = threadIdx.x;
    const int ty = threadIdx.y;

    const float* __restrict__ ip = in + ((size_t)b * C_CH + c0) * HW + p0;
    #pragma unroll
    for (int k = 0; k < 8; ++k) {
        const int c = ty + 8 * k;
        tile[c][tx] = __ldg(ip + (size_t)c * HW + tx);
    }
    __syncthreads();

    const int tid = ty * 32 + tx;
    const int cl  = tid & 31;            // channel pair
    const int r   = tid >> 5;            // 0..7
    __half2* __restrict__ op =
        (__half2*)(outp + ((size_t)b * HW + p0) * C_CH + c0) + cl;
    #pragma unroll
    for (int m = 0; m < 4; ++m) {
        const int pix = r + 8 * m;
        op[(size_t)pix * (C_CH / 2)] =
            __floats2half2_rn(tile[2 * cl][pix], tile[2 * cl + 1][pix]);
    }
}

__device__ __forceinline__ unsigned int h2_as_u32(__half2 h)
{
    return *(unsigned int*)&h;
}
__device__ __forceinline__ __half2 u32_as_h2(unsigned int u)
{
    return *(__half2*)&u;
}

// One fp16 tap over all 256 channels: lane owns 8 ch (uint4 = 16B).
__device__ __forceinline__ void tap4(const uint4* __restrict__ T,
                                     int p, __half2 w, __half2 a[4])
{
    const uint4 r = __ldg(T + p);
    a[0] = __hfma2(w, u32_as_h2(r.x), a[0]);
    a[1] = __hfma2(w, u32_as_h2(r.y), a[1]);
    a[2] = __hfma2(w, u32_as_h2(r.z), a[2]);
    a[3] = __hfma2(w, u32_as_h2(r.w), a[3]);
}

// -------- main kernel: block = (roi n, ph-split), 224 threads = 7 warps ----
// warp w handles pw = w*5 .. w*5+4; lane owns 8 consecutive channels.
// One LDG.128 per tap covers all 256 channels. ph loop inside block.
__global__ __launch_bounds__(224, 4)
void rroi_main_kernel(const float* __restrict__ rois, float* __restrict__ out)
{
    __shared__ int4         s_pix[ENTRIES];     // tap pixel idx, uint4 units
    __shared__ uint4        s_wt[ENTRIES];      // 4 dup'd half2 weights
    __shared__ unsigned int s_outh[OUT_W * 133];// [pw][c/2] as half2, pad 133

    const int n    = blockIdx.x;
    const int tid  = threadIdx.x;
    const int lane = tid & 31;
    const int wrp  = tid >> 5;          // 0..6

    const float r1 = __ldg(rois + n * 6 + 1);
    const float r2 = __ldg(rois + n * 6 + 2);
    const float r3 = __ldg(rois + n * 6 + 3);
    const float r4 = __ldg(rois + n * 6 + 4);
    const float r5 = __ldg(rois + n * 6 + 5);
    const int   b  = (int)__ldg(rois + n * 6 + 0);
    float sint, cost;
    sincosf(r5, &sint, &cost);

    const uint4* __restrict__ T0 = (const uint4*)g_h0;
    const uint4* __restrict__ T1 = (const uint4*)g_h1;
    const uint4* __restrict__ T2 = (const uint4*)g_h2;
    const uint4* __restrict__ T3 = (const uint4*)g_h3;

    const int ph_lo = blockIdx.y ? 4 : 0;
    const int ph_hi = blockIdx.y ? OUT_H : 4;

    for (int ph = ph_lo; ph < ph_hi; ++ph) {
        // ---- Phase 1: descriptors for this ph ----
        for (int e = tid; e < ENTRIES; e += 224) {
            const int pw  = e % OUT_W;
            const int q   = e / OUT_W;
            const int lev = q >> 2;
            const int s   = q & 3;
            const int sy  = s >> 1;
            const int sx  = s & 1;

            const int   Hc = 256 >> lev;
            const int   HW = Hc * Hc;
            const float sc = 0.25f / (float)(1 << lev);

            const float cx = r1 * sc;
            const float cy = r2 * sc;
            const float w  = fmaxf(r3 * sc, 1.0f);
            const float h  = fmaxf(r4 * sc, 1.0f);

            const float gy = (float)ph + ((float)sy + 0.5f) * 0.5f;
            const float gx = (float)pw + ((float)sx + 0.5f) * 0.5f;
            const float yy = gy * (h * (1.0f / OUT_H)) - 0.5f * h;
            const float xx = gx * (w * (1.0f / OUT_W)) - 0.5f * w;

            float x = xx * cost - yy * sint + cx;
            float y = xx * sint + yy * cost + cy;

            const float Hf = (float)Hc;
            const bool valid = (y >= -1.0f) && (y <= Hf) && (x >= -1.0f) && (x <= Hf);
            y = fminf(fmaxf(y, 0.0f), Hf - 1.0f);
            x = fminf(fmaxf(x, 0.0f), Hf - 1.0f);

            const int y0 = (int)floorf(y);
            const int x0 = (int)floorf(x);
            const int y1 = min(y0 + 1, Hc - 1);
            const int x1 = min(x0 + 1, Hc - 1);
            const float ly = y - (float)y0;
            const float lx = x - (float)x0;
            const float hy = 1.0f - ly;
            const float hx = 1.0f - lx;
            const float qv = valid ? 0.25f : 0.0f;

            const int base = b * HW;
            // uint4 units: 256 ch * 2B / 16B = 32 per pixel
            s_pix[e] = make_int4((base + y0 * Hc + x0) * 32,
                                 (base + y0 * Hc + x1) * 32,
                                 (base + y1 * Hc + x0) * 32,
                                 (base + y1 * Hc + x1) * 32);
            s_wt[e] = make_uint4(h2_as_u32(__float2half2_rn(hy * hx * qv)),
                                 h2_as_u32(__float2half2_rn(hy * lx * qv)),
                                 h2_as_u32(__float2half2_rn(ly * hx * qv)),
                                 h2_as_u32(__float2half2_rn(ly * lx * qv)));
        }
        __syncthreads();

        // ---- Phase 2: gathers (one LDG.128 per tap, 256 ch) ----
        #pragma unroll
        for (int pwi = 0; pwi < 5; ++pwi) {
            const int pw = wrp * 5 + pwi;
            __half2 best[4];
            #pragma unroll
            for (int lev = 0; lev < 4; ++lev) {
                const uint4* __restrict__ T =
                    (lev == 0) ? T0 : (lev == 1) ? T1 : (lev == 2) ? T2 : T3;
                float acc[8] = {0.f, 0.f, 0.f, 0.f, 0.f, 0.f, 0.f, 0.f};
                #pragma unroll
                for (int s2 = 0; s2 < 2; ++s2) {   // 2 samples per half2 chain
                    __half2 a[4];
                    a[0] = __float2half2_rn(0.f);
                    a[1] = a[0]; a[2] = a[0]; a[3] = a[0];
                    #pragma unroll
                    for (int ss = 0; ss < 2; ++ss) {
                        const int e = (lev * 4 + s2 * 2 + ss) * OUT_W + pw;
                        const int4  p = s_pix[e];
                        const uint4 w = s_wt[e];
                        tap4(T, p.x + lane, u32_as_h2(w.x), a);
                        tap4(T, p.y + lane, u32_as_h2(w.y), a);
                        tap4(T, p.z + lane, u32_as_h2(w.z), a);
                        tap4(T, p.w + lane, u32_as_h2(w.w), a);
                    }
                    #pragma unroll
                    for (int k = 0; k < 4; ++k) {
                        const float2 f = __half22float2(a[k]);
                        acc[2 * k]     += f.x;
                        acc[2 * k + 1] += f.y;
                    }
                }
                #pragma unroll
                for (int k = 0; k < 4; ++k) {
                    const __half2 h2 = __floats2half2_rn(acc[2 * k], acc[2 * k + 1]);
                    best[k] = (lev == 0) ? h2 : __hmax2(best[k], h2);
                }
            }
            #pragma unroll
            for (int k = 0; k < 4; ++k)
                s_outh[pw * 133 + lane * 4 + k] = h2_as_u32(best[k]);
        }
        __syncthreads();

        // ---- Phase 3: coalesced fp32 output write for this ph ----
        float* __restrict__ ob = out + (((size_t)n * C_CH) * OUT_H + ph) * OUT_W;
        for (int idx = tid; idx < C_CH * OUT_W; idx += 224) {
            const int c  = idx / OUT_W;
            const int pw = idx - c * OUT_W;
            const __half2 hv = u32_as_h2(s_outh[pw * 133 + (c >> 1)]);
            ob[(size_t)c * (OUT_H * OUT_W) + pw] =
                (c & 1) ? __high2float(hv) : __low2float(hv);
        }
        __syncthreads();
    }
}

extern "C" void kernel_launch(void* const* d_in, const int* in_sizes, int n_in,
                              void* d_out, int out_size)
{
    const float* f0   = (const float*)d_in[0];
    const float* f1   = (const float*)d_in[1];
    const float* f2   = (const float*)d_in[2];
    const float* f3   = (const float*)d_in[3];
    const float* rois = (const float*)d_in[4];
    float* out = (float*)d_out;

    const int N = in_sizes[4] / 6;

    transpose_all_kernel<<<NB_ALL, dim3(32, 8)>>>(f0, f1, f2, f3);
    rroi_main_kernel<<<dim3(N, 2), 224>>>(rois, out);
}